// round 5
// baseline (speedup 1.0000x reference)
#include <cuda_runtime.h>
#include <math.h>

namespace {
constexpr int B = 8, S = 4096, E = 1024, H = 8, W = 128, D = 128;
constexpr int NWIN = S / W;          // 32
constexpr int TPAD = 132;            // padded row stride (floats) for transposed smem tiles
constexpr float SCALE = 0.08838834764831845f;  // D^-0.5
}

// Scratch (device globals — no runtime allocation allowed)
__device__ float g_q[(size_t)B * H * S * D];
__device__ float g_k[(size_t)B * H * S * D];
__device__ float g_v[(size_t)B * H * S * D];
__device__ float g_att[(size_t)B * S * E];

// ---------------------------------------------------------------------------
// Tile loaders: 128x128 fp32 tile, 256 threads.
// Coalesced float4 gmem reads (one warp = one 512B row), scatter into smem.
// ---------------------------------------------------------------------------

// Transposed: smT[col][row], row stride TPAD. Optional scale folded in.
__device__ __forceinline__ void load_tile_T(const float* __restrict__ g, int row_stride,
                                            float* __restrict__ smT, int t, float scale)
{
#pragma unroll
    for (int v = 0; v < 16; v++) {
        int lin = t + v * 256;          // quad index 0..4095
        int row = lin >> 5;             // 0..127
        int qc  = (lin & 31) << 2;      // column base 0..124
        float4 f = *reinterpret_cast<const float4*>(g + (long)row * row_stride + qc);
        smT[(qc + 0) * TPAD + row] = f.x * scale;
        smT[(qc + 1) * TPAD + row] = f.y * scale;
        smT[(qc + 2) * TPAD + row] = f.z * scale;
        smT[(qc + 3) * TPAD + row] = f.w * scale;
    }
}

// Natural: sm[row][col], row stride 128 (float4-aligned).
__device__ __forceinline__ void load_tile_N(const float* __restrict__ g, int row_stride,
                                            float* __restrict__ sm, int t)
{
#pragma unroll
    for (int v = 0; v < 16; v++) {
        int lin = t + v * 256;
        int row = lin >> 5;
        int qc  = (lin & 31) << 2;
        *reinterpret_cast<float4*>(sm + row * 128 + qc) =
            *reinterpret_cast<const float4*>(g + (long)row * row_stride + qc);
    }
}

// ---------------------------------------------------------------------------
// Kernel 1: per-head projection. out[b,h,s,o] = sum_d x[b,s,h*D+d] * Wt[o,d]
// grid (S/128, H, B), 256 threads, 8x8 register tile per thread.
// ---------------------------------------------------------------------------
__global__ void __launch_bounds__(256)
proj_kernel(const float* __restrict__ x, const float* __restrict__ Wt,
            float* __restrict__ out)
{
    extern __shared__ float sm[];
    float* xsT = sm;                 // [128][TPAD]  xsT[d][row]
    float* WsT = sm + 128 * TPAD;    // [128][TPAD]  WsT[d][o]

    const int t  = threadIdx.x;
    const int st = blockIdx.x, h = blockIdx.y, b = blockIdx.z;
    const int s0 = st * 128;

    load_tile_T(x + ((long)(b * S + s0)) * E + h * D, E, xsT, t, 1.0f);
    load_tile_T(Wt, D, WsT, t, 1.0f);
    __syncthreads();

    const int r0 = (t >> 4) << 3;
    const int c0 = (t & 15) << 3;
    float acc[8][8] = {};

#pragma unroll 4
    for (int kk = 0; kk < 128; kk++) {
        float4 a0 = *reinterpret_cast<float4*>(&xsT[kk * TPAD + r0]);
        float4 a1 = *reinterpret_cast<float4*>(&xsT[kk * TPAD + r0 + 4]);
        float4 b0 = *reinterpret_cast<float4*>(&WsT[kk * TPAD + c0]);
        float4 b1 = *reinterpret_cast<float4*>(&WsT[kk * TPAD + c0 + 4]);
        float a[8] = {a0.x, a0.y, a0.z, a0.w, a1.x, a1.y, a1.z, a1.w};
        float bb[8] = {b0.x, b0.y, b0.z, b0.w, b1.x, b1.y, b1.z, b1.w};
#pragma unroll
        for (int i = 0; i < 8; i++)
#pragma unroll
            for (int j = 0; j < 8; j++)
                acc[i][j] = fmaf(a[i], bb[j], acc[i][j]);
    }

    long ob = ((long)(b * H + h) * S + s0 + r0) * D + c0;
#pragma unroll
    for (int i = 0; i < 8; i++) {
        *reinterpret_cast<float4*>(&out[ob + (long)i * D]) =
            make_float4(acc[i][0], acc[i][1], acc[i][2], acc[i][3]);
        *reinterpret_cast<float4*>(&out[ob + (long)i * D + 4]) =
            make_float4(acc[i][4], acc[i][5], acc[i][6], acc[i][7]);
    }
}

// ---------------------------------------------------------------------------
// Kernel 2: sliding-window attention. One block per (window, head, batch).
// Flash-style over the 3 neighbor windows; skipped out-of-range window ==
// reference's finfo.min mask (exp underflows to exactly 0).
// Output layout [b, s, h*D+d] so fc_out reads contiguously.
// ---------------------------------------------------------------------------
__global__ void __launch_bounds__(256)
attn_kernel(const float* __restrict__ gq, const float* __restrict__ gk,
            const float* __restrict__ gv, float* __restrict__ gout)
{
    extern __shared__ float sm[];
    float* qsT = sm;                               // [128][TPAD]  q^T (pre-scaled)
    float* ksT = sm + 128 * TPAD;                  // [128][TPAD]  k^T, reused as p^T
    float* vs  = sm + 2 * 128 * TPAD;              // [128][128]   v natural

    const int t  = threadIdx.x;
    const int wi = blockIdx.x, h = blockIdx.y, b = blockIdx.z;
    const long base = (long)(b * H + h) * S * D;

    load_tile_T(gq + base + (long)wi * W * D, D, qsT, t, SCALE);

    const int r0 = (t >> 4) << 3;   // query rows owned
    const int c0 = (t & 15) << 3;   // key cols (phase 1) / d cols (phase 2)

    float m[8], l[8], acc[8][8] = {};
#pragma unroll
    for (int i = 0; i < 8; i++) { m[i] = -1e30f; l[i] = 0.0f; }

    for (int c = 0; c < 3; c++) {
        const int j = wi - 1 + c;
        if (j < 0 || j >= NWIN) continue;     // uniform across block

        __syncthreads();  // previous PV done reading ksT/vs; qsT load visible
        load_tile_T(gk + base + (long)j * W * D, D, ksT, t, 1.0f);
        load_tile_N(gv + base + (long)j * W * D, D, vs, t);
        __syncthreads();

        // --- S = q k^T (scaled) ---
        float s[8][8] = {};
#pragma unroll 4
        for (int kk = 0; kk < 128; kk++) {
            float4 a0 = *reinterpret_cast<float4*>(&qsT[kk * TPAD + r0]);
            float4 a1 = *reinterpret_cast<float4*>(&qsT[kk * TPAD + r0 + 4]);
            float4 b0 = *reinterpret_cast<float4*>(&ksT[kk * TPAD + c0]);
            float4 b1 = *reinterpret_cast<float4*>(&ksT[kk * TPAD + c0 + 4]);
            float a[8] = {a0.x, a0.y, a0.z, a0.w, a1.x, a1.y, a1.z, a1.w};
            float bb[8] = {b0.x, b0.y, b0.z, b0.w, b1.x, b1.y, b1.z, b1.w};
#pragma unroll
            for (int i = 0; i < 8; i++)
#pragma unroll
                for (int jj = 0; jj < 8; jj++)
                    s[i][jj] = fmaf(a[i], bb[jj], s[i][jj]);
        }

        // --- online softmax (row stats across the 16-lane tx group) ---
        float mn[8], alpha[8];
#pragma unroll
        for (int i = 0; i < 8; i++) {
            float cm = s[i][0];
#pragma unroll
            for (int jj = 1; jj < 8; jj++) cm = fmaxf(cm, s[i][jj]);
#pragma unroll
            for (int off = 8; off >= 1; off >>= 1)
                cm = fmaxf(cm, __shfl_xor_sync(0xffffffffu, cm, off));
            mn[i] = fmaxf(m[i], cm);
            alpha[i] = __expf(m[i] - mn[i]);
            float rs = 0.0f;
#pragma unroll
            for (int jj = 0; jj < 8; jj++) {
                s[i][jj] = __expf(s[i][jj] - mn[i]);
                rs += s[i][jj];
            }
#pragma unroll
            for (int off = 8; off >= 1; off >>= 1)
                rs += __shfl_xor_sync(0xffffffffu, rs, off);
            l[i] = l[i] * alpha[i] + rs;
            m[i] = mn[i];
        }
#pragma unroll
        for (int i = 0; i < 8; i++)
#pragma unroll
            for (int jj = 0; jj < 8; jj++) acc[i][jj] *= alpha[i];

        // --- write p^T into ksT (all reads of k finished) ---
        __syncthreads();
#pragma unroll
        for (int jj = 0; jj < 8; jj++) {
            *reinterpret_cast<float4*>(&ksT[(c0 + jj) * TPAD + r0]) =
                make_float4(s[0][jj], s[1][jj], s[2][jj], s[3][jj]);
            *reinterpret_cast<float4*>(&ksT[(c0 + jj) * TPAD + r0 + 4]) =
                make_float4(s[4][jj], s[5][jj], s[6][jj], s[7][jj]);
        }
        __syncthreads();

        // --- acc += p v ---
#pragma unroll 4
        for (int kk = 0; kk < 128; kk++) {
            float4 a0 = *reinterpret_cast<float4*>(&ksT[kk * TPAD + r0]);
            float4 a1 = *reinterpret_cast<float4*>(&ksT[kk * TPAD + r0 + 4]);
            float4 b0 = *reinterpret_cast<float4*>(&vs[kk * 128 + c0]);
            float4 b1 = *reinterpret_cast<float4*>(&vs[kk * 128 + c0 + 4]);
            float a[8] = {a0.x, a0.y, a0.z, a0.w, a1.x, a1.y, a1.z, a1.w};
            float bb[8] = {b0.x, b0.y, b0.z, b0.w, b1.x, b1.y, b1.z, b1.w};
#pragma unroll
            for (int i = 0; i < 8; i++)
#pragma unroll
                for (int jj = 0; jj < 8; jj++)
                    acc[i][jj] = fmaf(a[i], bb[jj], acc[i][jj]);
        }
    }

    // epilogue: normalize, store to [b, s, h*D + d]
#pragma unroll
    for (int i = 0; i < 8; i++) {
        float inv = 1.0f / l[i];
        long ob = ((long)(b * S + wi * W + r0 + i)) * E + h * D + c0;
        *reinterpret_cast<float4*>(&gout[ob]) =
            make_float4(acc[i][0] * inv, acc[i][1] * inv, acc[i][2] * inv, acc[i][3] * inv);
        *reinterpret_cast<float4*>(&gout[ob + 4]) =
            make_float4(acc[i][4] * inv, acc[i][5] * inv, acc[i][6] * inv, acc[i][7] * inv);
    }
}

// ---------------------------------------------------------------------------
// Kernel 3: fc_out. y[m,o] = sum_e att[m,e]*Wo[o,e] + bo[o]
// M = B*S = 32768, N = K = 1024. grid (N/128, M/128), 128x128 tile, KC=64.
// ---------------------------------------------------------------------------
__global__ void __launch_bounds__(256)
fc_kernel(const float* __restrict__ att, const float* __restrict__ Wo,
          const float* __restrict__ bo, float* __restrict__ y)
{
    extern __shared__ float sm[];
    float* aT = sm;               // [64][TPAD]  a^T chunk
    float* bT = sm + 64 * TPAD;   // [64][TPAD]  Wo^T chunk

    const int t  = threadIdx.x;
    const int n0 = blockIdx.x * 128;
    const int m0 = blockIdx.y * 128;
    const int r0 = (t >> 4) << 3;
    const int c0 = (t & 15) << 3;

    float acc[8][8] = {};

    for (int e0 = 0; e0 < E; e0 += 64) {
        __syncthreads();
#pragma unroll
        for (int v = 0; v < 8; v++) {
            int lin = t + v * 256;       // quad index 0..2047
            int row = lin >> 4;          // 0..127
            int qc  = (lin & 15) << 2;   // 0..60
            float4 f = *reinterpret_cast<const float4*>(att + (long)(m0 + row) * E + e0 + qc);
            aT[(qc + 0) * TPAD + row] = f.x;
            aT[(qc + 1) * TPAD + row] = f.y;
            aT[(qc + 2) * TPAD + row] = f.z;
            aT[(qc + 3) * TPAD + row] = f.w;
            float4 g = *reinterpret_cast<const float4*>(Wo + (long)(n0 + row) * E + e0 + qc);
            bT[(qc + 0) * TPAD + row] = g.x;
            bT[(qc + 1) * TPAD + row] = g.y;
            bT[(qc + 2) * TPAD + row] = g.z;
            bT[(qc + 3) * TPAD + row] = g.w;
        }
        __syncthreads();

#pragma unroll 4
        for (int kk = 0; kk < 64; kk++) {
            float4 a0 = *reinterpret_cast<float4*>(&aT[kk * TPAD + r0]);
            float4 a1 = *reinterpret_cast<float4*>(&aT[kk * TPAD + r0 + 4]);
            float4 b0 = *reinterpret_cast<float4*>(&bT[kk * TPAD + c0]);
            float4 b1 = *reinterpret_cast<float4*>(&bT[kk * TPAD + c0 + 4]);
            float a[8] = {a0.x, a0.y, a0.z, a0.w, a1.x, a1.y, a1.z, a1.w};
            float bb[8] = {b0.x, b0.y, b0.z, b0.w, b1.x, b1.y, b1.z, b1.w};
#pragma unroll
            for (int i = 0; i < 8; i++)
#pragma unroll
                for (int jj = 0; jj < 8; jj++)
                    acc[i][jj] = fmaf(a[i], bb[jj], acc[i][jj]);
        }
    }

    float bias[8];
#pragma unroll
    for (int jj = 0; jj < 8; jj++) bias[jj] = bo[n0 + c0 + jj];

#pragma unroll
    for (int i = 0; i < 8; i++) {
        long ob = (long)(m0 + r0 + i) * E + n0 + c0;
        *reinterpret_cast<float4*>(&y[ob]) =
            make_float4(acc[i][0] + bias[0], acc[i][1] + bias[1],
                        acc[i][2] + bias[2], acc[i][3] + bias[3]);
        *reinterpret_cast<float4*>(&y[ob + 4]) =
            make_float4(acc[i][4] + bias[4], acc[i][5] + bias[5],
                        acc[i][6] + bias[6], acc[i][7] + bias[7]);
    }
}

// ---------------------------------------------------------------------------
// Launcher
// ---------------------------------------------------------------------------
extern "C" void kernel_launch(void* const* d_in, const int* in_sizes, int n_in,
                              void* d_out, int out_size)
{
    const float* values = (const float*)d_in[0];
    const float* keys   = (const float*)d_in[1];
    const float* query  = (const float*)d_in[2];
    const float* Wv     = (const float*)d_in[3];
    const float* Wk     = (const float*)d_in[4];
    const float* Wq     = (const float*)d_in[5];
    const float* Wo     = (const float*)d_in[6];
    const float* bo     = (const float*)d_in[7];
    float* out = (float*)d_out;

    float *q, *k, *v, *att;
    cudaGetSymbolAddress((void**)&q, g_q);
    cudaGetSymbolAddress((void**)&k, g_k);
    cudaGetSymbolAddress((void**)&v, g_v);
    cudaGetSymbolAddress((void**)&att, g_att);

    const size_t proj_smem = (size_t)2 * 128 * TPAD * sizeof(float);              // 135168
    const size_t attn_smem = ((size_t)2 * 128 * TPAD + 128 * 128) * sizeof(float); // 200704
    const size_t fc_smem   = (size_t)2 * 64 * TPAD * sizeof(float);               // 67584

    cudaFuncSetAttribute(proj_kernel, cudaFuncAttributeMaxDynamicSharedMemorySize, (int)proj_smem);
    cudaFuncSetAttribute(attn_kernel, cudaFuncAttributeMaxDynamicSharedMemorySize, (int)attn_smem);
    cudaFuncSetAttribute(fc_kernel,   cudaFuncAttributeMaxDynamicSharedMemorySize, (int)fc_smem);

    dim3 pg(S / 128, H, B);
    proj_kernel<<<pg, 256, proj_smem>>>(query,  Wq, q);
    proj_kernel<<<pg, 256, proj_smem>>>(keys,   Wk, k);
    proj_kernel<<<pg, 256, proj_smem>>>(values, Wv, v);

    attn_kernel<<<dim3(NWIN, H, B), 256, attn_smem>>>(q, k, v, att);

    fc_kernel<<<dim3(E / 128, (B * S) / 128), 256, fc_smem>>>(att, Wo, bo, out);
}

// round 7
// speedup vs baseline: 2.1983x; 2.1983x over previous
#include <cuda_runtime.h>
#include <cuda_bf16.h>
#include <cstdint>

namespace {
constexpr int Bb = 8, S = 4096, E = 1024, H = 8, D = 128, NW = 32;
constexpr float SCALE = 0.08838834764831845f;  // D^-0.5
}

// intermediates: bf16 hi/lo, plain row-major (device globals; no runtime alloc)
__device__ __nv_bfloat16 g_qh[(size_t)Bb*H*S*D], g_ql[(size_t)Bb*H*S*D];
__device__ __nv_bfloat16 g_kh[(size_t)Bb*H*S*D], g_kl[(size_t)Bb*H*S*D];
__device__ __nv_bfloat16 g_vh[(size_t)Bb*H*S*D], g_vl[(size_t)Bb*H*S*D];
__device__ __nv_bfloat16 g_ah[(size_t)Bb*S*E],   g_al[(size_t)Bb*S*E];
__device__ __nv_bfloat16 g_woh[(size_t)E*E],     g_wol[(size_t)E*E];

// ---------------- helpers ----------------
__device__ __forceinline__ uint32_t smem_u32(const void* p) {
    uint32_t a;
    asm("{ .reg .u64 t; cvta.to.shared.u64 t, %1; cvt.u32.u64 %0, t; }" : "=r"(a) : "l"(p));
    return a;
}
// swizzled 128x128 bf16 tile (32KB): row r (256B), 16B chunk c XOR'd with r&7
__device__ __forceinline__ uint32_t toff(int r, int cbyte) {
    return (uint32_t)(r * 256 + ((((cbyte >> 4) ^ (r & 7)) << 4) | (cbyte & 15)));
}
__device__ __forceinline__ void ldm_x4(uint32_t* a, uint32_t addr) {
    asm volatile("ldmatrix.sync.aligned.m8n8.x4.shared.b16 {%0,%1,%2,%3}, [%4];"
        : "=r"(a[0]), "=r"(a[1]), "=r"(a[2]), "=r"(a[3]) : "r"(addr));
}
__device__ __forceinline__ void ldm_x2(uint32_t* b, uint32_t addr) {
    asm volatile("ldmatrix.sync.aligned.m8n8.x2.shared.b16 {%0,%1}, [%2];"
        : "=r"(b[0]), "=r"(b[1]) : "r"(addr));
}
__device__ __forceinline__ void ldm_x2t(uint32_t* b, uint32_t addr) {
    asm volatile("ldmatrix.sync.aligned.m8n8.x2.trans.shared.b16 {%0,%1}, [%2];"
        : "=r"(b[0]), "=r"(b[1]) : "r"(addr));
}
__device__ __forceinline__ void mma16816(float* c, const uint32_t* a, const uint32_t* b) {
    asm volatile("mma.sync.aligned.m16n8k16.row.col.f32.bf16.bf16.f32 "
        "{%0,%1,%2,%3},{%4,%5,%6,%7},{%8,%9},{%0,%1,%2,%3};"
        : "+f"(c[0]), "+f"(c[1]), "+f"(c[2]), "+f"(c[3])
        : "r"(a[0]), "r"(a[1]), "r"(a[2]), "r"(a[3]), "r"(b[0]), "r"(b[1]));
}
// warp 128x128x128 tile pass: warp computes rows [m0,m0+32) x cols [n0,n0+64)
template<bool TB>
__device__ __forceinline__ void gemm128(uint32_t aB, uint32_t bB, float acc[2][8][4],
                                        int lane, int m0, int n0) {
#pragma unroll
    for (int ks = 0; ks < 8; ks++) {
        uint32_t a[2][4];
#pragma unroll
        for (int mt = 0; mt < 2; mt++)
            ldm_x4(a[mt], aB + toff(m0 + mt * 16 + (lane & 15), ks * 32 + ((lane >> 4) << 4)));
#pragma unroll
        for (int nt = 0; nt < 8; nt++) {
            uint32_t b[2];
            if (!TB) ldm_x2 (b, bB + toff(n0 + nt * 8 + (lane & 7), ks * 32 + (((lane >> 3) & 1) << 4)));
            else     ldm_x2t(b, bB + toff(ks * 16 + (lane & 15), (n0 + nt * 8) * 2));
            mma16816(acc[0][nt], a[0], b);
            mma16816(acc[1][nt], a[1], b);
        }
    }
}
__device__ __forceinline__ void split2(float a, float b, uint32_t& hi, uint32_t& lo) {
    __nv_bfloat16 ha = __float2bfloat16(a), hb = __float2bfloat16(b);
    __nv_bfloat16 la = __float2bfloat16(a - __bfloat162float(ha));
    __nv_bfloat16 lb = __float2bfloat16(b - __bfloat162float(hb));
    hi = ((uint32_t)__bfloat16_as_ushort(hb) << 16) | __bfloat16_as_ushort(ha);
    lo = ((uint32_t)__bfloat16_as_ushort(lb) << 16) | __bfloat16_as_ushort(la);
}
// fp32 [128x128] (ld) -> hi/lo swizzled tiles
__device__ __forceinline__ void cvt_tile(const float* __restrict__ g, int ld,
                                         char* sh, char* sl, int t) {
#pragma unroll
    for (int it = 0; it < 8; it++) {
        int r = (t >> 4) + it * 16, c8 = t & 15;
        const float* p = g + (size_t)r * ld + c8 * 8;
        float x[8];
        *(float4*)x = *(const float4*)p;
        *(float4*)(x + 4) = *(const float4*)(p + 4);
        uint32_t h[4], l[4];
#pragma unroll
        for (int j = 0; j < 4; j++) split2(x[j * 2], x[j * 2 + 1], h[j], l[j]);
        uint32_t o = toff(r, c8 * 16);
        *(uint4*)(sh + o) = *(uint4*)h;
        *(uint4*)(sl + o) = *(uint4*)l;
    }
}
// bf16 rows (ld elems) -> swizzled tile
__device__ __forceinline__ void cp_tile(const __nv_bfloat16* __restrict__ g, int ld,
                                        char* s, int t) {
#pragma unroll
    for (int it = 0; it < 8; it++) {
        int r = (t >> 4) + it * 16, c8 = t & 15;
        *(uint4*)(s + toff(r, c8 * 16)) = *(const uint4*)(g + (size_t)r * ld + c8 * 8);
    }
}
// MUFU-free exp (ldexp + 2^f poly), rel err ~2e-8
__device__ __forceinline__ float fast_exp(float x) {
    float y = x * 1.4426950408889634f;
    float z = y + 12582912.0f;
    int   n = __float_as_int(z) - 0x4B400000;
    float f = y - (z - 12582912.0f);
    float p = fmaf(f, 1.5403530e-4f, 1.3333558e-3f);
    p = fmaf(f, p, 9.6181291e-3f);
    p = fmaf(f, p, 5.5504109e-2f);
    p = fmaf(f, p, 2.4022651e-1f);
    p = fmaf(f, p, 6.9314718e-1f);
    p = fmaf(f, p, 1.0f);
    return __int_as_float(__float_as_int(p) + (n << 23));
}

// ---------------- prep: Wo fp32 -> hi/lo bf16 rows ----------------
__global__ void __launch_bounds__(256) prep_wo_kernel(const float* __restrict__ Wo) {
    int idx = blockIdx.x * 256 + threadIdx.x;     // 131072 chunks of 8
    int r = idx >> 7, c8 = idx & 127;
    const float* p = Wo + (size_t)r * E + c8 * 8;
    float x[8];
    *(float4*)x = *(const float4*)p;
    *(float4*)(x + 4) = *(const float4*)(p + 4);
    uint32_t h[4], l[4];
#pragma unroll
    for (int j = 0; j < 4; j++) split2(x[j * 2], x[j * 2 + 1], h[j], l[j]);
    *(uint4*)(g_woh + (size_t)r * E + c8 * 8) = *(uint4*)h;
    *(uint4*)(g_wol + (size_t)r * E + c8 * 8) = *(uint4*)l;
}

// ---------------- proj: out[s,o] = x[s,:] @ W[o,:]^T (per head) ----------------
__global__ void __launch_bounds__(256)
proj_kernel(const float* __restrict__ x, const float* __restrict__ Wt,
            __nv_bfloat16* __restrict__ oh, __nv_bfloat16* __restrict__ ol, float scale) {
    extern __shared__ char sm[];
    uint32_t sb = smem_u32(sm);
    const int t = threadIdx.x, lane = t & 31, wid = t >> 5;
    const int w = blockIdx.x, h = blockIdx.y, b = blockIdx.z;

    cvt_tile(x + ((size_t)(b * S + w * 128)) * E + h * D, E, sm, sm + 32768, t);
    cvt_tile(Wt, D, sm + 65536, sm + 98304, t);
    __syncthreads();

    const int m0 = (wid & 3) * 32, n0 = (wid >> 2) * 64;
    float acc[2][8][4] = {};
    gemm128<false>(sb,         sb + 65536, acc, lane, m0, n0);
    gemm128<false>(sb,         sb + 98304, acc, lane, m0, n0);
    gemm128<false>(sb + 32768, sb + 65536, acc, lane, m0, n0);

    size_t base = ((size_t)(b * H + h) * S + w * 128);
#pragma unroll
    for (int mt = 0; mt < 2; mt++)
#pragma unroll
        for (int hf = 0; hf < 2; hf++) {
            int r = m0 + mt * 16 + (lane >> 2) + hf * 8;
            size_t row = (base + r) * D;
#pragma unroll
            for (int nt = 0; nt < 8; nt++) {
                int c = n0 + nt * 8 + (lane & 3) * 2;
                uint32_t hi, lo;
                split2(acc[mt][nt][hf * 2] * scale, acc[mt][nt][hf * 2 + 1] * scale, hi, lo);
                *(uint32_t*)(oh + row + c) = hi;
                *(uint32_t*)(ol + row + c) = lo;
            }
        }
}

// ---------------- attention (per window,head,batch) ----------------
__global__ void __launch_bounds__(256)
attn_kernel() {
    extern __shared__ char sm[];
    // Qh 0 | Ql 32K | Kh/Ph 64K | Kl/Pl 96K | Vh 128K | Vl 160K | Lacc 192K
    uint32_t sb = smem_u32(sm);
    float* Lacc = (float*)(sm + 196608);
    const int t = threadIdx.x, lane = t & 31, wid = t >> 5;
    const int w = blockIdx.x, h = blockIdx.y, b = blockIdx.z;
    const size_t base = (size_t)((b * H + h) * S);

    cp_tile(g_qh + (base + w * 128) * D, D, sm, t);
    cp_tile(g_ql + (base + w * 128) * D, D, sm + 32768, t);
    if (t < 128) Lacc[t] = 0.0f;

    const int m0 = (wid & 3) * 32, n0 = (wid >> 2) * 64;
    float oacc[2][8][4] = {};

    for (int j = w - 1; j <= w + 1; j++) {
        if (j < 0 || j >= NW) continue;
        __syncthreads();   // prev PV reads done; Q/Lacc visible on first pass
        cp_tile(g_kh + (base + j * 128) * D, D, sm + 65536,  t);
        cp_tile(g_kl + (base + j * 128) * D, D, sm + 98304,  t);
        cp_tile(g_vh + (base + j * 128) * D, D, sm + 131072, t);
        cp_tile(g_vl + (base + j * 128) * D, D, sm + 163840, t);
        __syncthreads();

        float sacc[2][8][4] = {};
        gemm128<false>(sb,         sb + 65536, sacc, lane, m0, n0);
        gemm128<false>(sb,         sb + 98304, sacc, lane, m0, n0);
        gemm128<false>(sb + 32768, sb + 65536, sacc, lane, m0, n0);
        __syncthreads();   // all warps done reading K before P overwrite

#pragma unroll
        for (int mt = 0; mt < 2; mt++)
#pragma unroll
            for (int hf = 0; hf < 2; hf++) {
                int r = m0 + mt * 16 + (lane >> 2) + hf * 8;
                float rsum = 0.0f;
#pragma unroll
                for (int nt = 0; nt < 8; nt++) {
                    float e0 = fast_exp(sacc[mt][nt][hf * 2]);
                    float e1 = fast_exp(sacc[mt][nt][hf * 2 + 1]);
                    rsum += e0 + e1;
                    uint32_t hi, lo;
                    split2(e0, e1, hi, lo);
                    int c = n0 + nt * 8 + (lane & 3) * 2;
                    uint32_t o = toff(r, c * 2);
                    *(uint32_t*)(sm + 65536 + o) = hi;
                    *(uint32_t*)(sm + 98304 + o) = lo;
                }
                rsum += __shfl_xor_sync(0xffffffffu, rsum, 1);
                rsum += __shfl_xor_sync(0xffffffffu, rsum, 2);
                if ((lane & 3) == 0) atomicAdd(&Lacc[r], rsum);
            }
        __syncthreads();

        gemm128<true>(sb + 65536, sb + 131072, oacc, lane, m0, n0);
        gemm128<true>(sb + 65536, sb + 163840, oacc, lane, m0, n0);
        gemm128<true>(sb + 98304, sb + 131072, oacc, lane, m0, n0);
    }
    __syncthreads();

#pragma unroll
    for (int mt = 0; mt < 2; mt++)
#pragma unroll
        for (int hf = 0; hf < 2; hf++) {
            int r = m0 + mt * 16 + (lane >> 2) + hf * 8;
            float inv = 1.0f / Lacc[r];
            size_t row = ((size_t)b * S + w * 128 + r) * E + h * D;
#pragma unroll
            for (int nt = 0; nt < 8; nt++) {
                int c = n0 + nt * 8 + (lane & 3) * 2;
                uint32_t hi, lo;
                split2(oacc[mt][nt][hf * 2] * inv, oacc[mt][nt][hf * 2 + 1] * inv, hi, lo);
                *(uint32_t*)(g_ah + row + c) = hi;
                *(uint32_t*)(g_al + row + c) = lo;
            }
        }
}

// ---------------- fc: y = att @ Wo^T + bo ----------------
__global__ void __launch_bounds__(256)
fc_kernel(const float* __restrict__ bo, float* __restrict__ y) {
    extern __shared__ char sm[];
    uint32_t sb = smem_u32(sm);
    const int t = threadIdx.x, lane = t & 31, wid = t >> 5;
    const int nb = blockIdx.x, mb = blockIdx.y;
    const int m0 = (wid & 3) * 32, n0 = (wid >> 2) * 64;

    float acc[2][8][4] = {};
    for (int kc = 0; kc < 8; kc++) {
        __syncthreads();
        cp_tile(g_ah  + (size_t)(mb * 128) * E + kc * 128, E, sm,         t);
        cp_tile(g_al  + (size_t)(mb * 128) * E + kc * 128, E, sm + 32768, t);
        cp_tile(g_woh + (size_t)(nb * 128) * E + kc * 128, E, sm + 65536, t);
        cp_tile(g_wol + (size_t)(nb * 128) * E + kc * 128, E, sm + 98304, t);
        __syncthreads();
        gemm128<false>(sb,         sb + 65536, acc, lane, m0, n0);
        gemm128<false>(sb,         sb + 98304, acc, lane, m0, n0);
        gemm128<false>(sb + 32768, sb + 65536, acc, lane, m0, n0);
    }

#pragma unroll
    for (int mt = 0; mt < 2; mt++)
#pragma unroll
        for (int hf = 0; hf < 2; hf++) {
            int r = m0 + mt * 16 + (lane >> 2) + hf * 8;
            size_t row = ((size_t)(mb * 128 + r)) * E + nb * 128;
#pragma unroll
            for (int nt = 0; nt < 8; nt++) {
                int c = n0 + nt * 8 + (lane & 3) * 2;
                float2 o;
                o.x = acc[mt][nt][hf * 2]     + bo[nb * 128 + c];
                o.y = acc[mt][nt][hf * 2 + 1] + bo[nb * 128 + c + 1];
                *(float2*)(y + row + c) = o;
            }
        }
}

// ---------------- launcher ----------------
extern "C" void kernel_launch(void* const* d_in, const int* in_sizes, int n_in,
                              void* d_out, int out_size) {
    const float* values = (const float*)d_in[0];
    const float* keys   = (const float*)d_in[1];
    const float* query  = (const float*)d_in[2];
    const float* Wv     = (const float*)d_in[3];
    const float* Wk     = (const float*)d_in[4];
    const float* Wq     = (const float*)d_in[5];
    const float* Wo     = (const float*)d_in[6];
    const float* bo     = (const float*)d_in[7];
    float* out = (float*)d_out;

    __nv_bfloat16 *qh, *ql, *kh, *kl, *vh, *vl;
    cudaGetSymbolAddress((void**)&qh, g_qh); cudaGetSymbolAddress((void**)&ql, g_ql);
    cudaGetSymbolAddress((void**)&kh, g_kh); cudaGetSymbolAddress((void**)&kl, g_kl);
    cudaGetSymbolAddress((void**)&vh, g_vh); cudaGetSymbolAddress((void**)&vl, g_vl);

    const int proj_smem = 131072;
    const int attn_smem = 196608 + 512;
    const int fc_smem   = 131072;
    cudaFuncSetAttribute(proj_kernel, cudaFuncAttributeMaxDynamicSharedMemorySize, proj_smem);
    cudaFuncSetAttribute(attn_kernel, cudaFuncAttributeMaxDynamicSharedMemorySize, attn_smem);
    cudaFuncSetAttribute(fc_kernel,   cudaFuncAttributeMaxDynamicSharedMemorySize, fc_smem);

    prep_wo_kernel<<<512, 256>>>(Wo);

    dim3 pg(NW, H, Bb);
    proj_kernel<<<pg, 256, proj_smem>>>(query,  Wq, qh, ql, SCALE);
    proj_kernel<<<pg, 256, proj_smem>>>(keys,   Wk, kh, kl, 1.0f);
    proj_kernel<<<pg, 256, proj_smem>>>(values, Wv, vh, vl, 1.0f);

    attn_kernel<<<pg, 256, attn_smem>>>();

    fc_kernel<<<dim3(E / 128, (Bb * S) / 128), 256, fc_smem>>>(bo, out);
}

// round 8
// speedup vs baseline: 2.8602x; 1.3011x over previous
#include <cuda_runtime.h>
#include <cuda_bf16.h>
#include <cstdint>

namespace {
constexpr int Bb = 8, S = 4096, E = 1024, H = 8, D = 128, NW = 32;
constexpr float SCALE = 0.08838834764831845f;  // D^-0.5
}

// intermediates: bf16 hi/lo, row-major (device globals; no runtime alloc)
__device__ __align__(128) __nv_bfloat16 g_qh[(size_t)Bb*H*S*D], g_ql[(size_t)Bb*H*S*D];
__device__ __align__(128) __nv_bfloat16 g_kh[(size_t)Bb*H*S*D], g_kl[(size_t)Bb*H*S*D];
__device__ __align__(128) __nv_bfloat16 g_vh[(size_t)Bb*H*S*D], g_vl[(size_t)Bb*H*S*D];
__device__ __align__(128) __nv_bfloat16 g_ah[(size_t)Bb*S*E],   g_al[(size_t)Bb*S*E];
__device__ __align__(128) __nv_bfloat16 g_woh[(size_t)E*E],     g_wol[(size_t)E*E];

// ---------------- low-level helpers ----------------
__device__ __forceinline__ uint32_t smem_u32(const void* p) {
    uint32_t a;
    asm("{ .reg .u64 t; cvta.to.shared.u64 t, %1; cvt.u32.u64 %0, t; }" : "=r"(a) : "l"(p));
    return a;
}
// swizzled tile offset: row r, col byte cb (16B granular), row bytes RB
template<int RB>
__device__ __forceinline__ uint32_t toff(int r, int cb) {
    return (uint32_t)(r * RB + ((((cb >> 4) ^ (r & 7)) & (RB / 16 - 1)) << 4) + (cb & 15));
}
__device__ __forceinline__ void ldm_x4(uint32_t* a, uint32_t addr) {
    asm volatile("ldmatrix.sync.aligned.m8n8.x4.shared.b16 {%0,%1,%2,%3}, [%4];"
        : "=r"(a[0]), "=r"(a[1]), "=r"(a[2]), "=r"(a[3]) : "r"(addr));
}
__device__ __forceinline__ void ldm_x2(uint32_t* b, uint32_t addr) {
    asm volatile("ldmatrix.sync.aligned.m8n8.x2.shared.b16 {%0,%1}, [%2];"
        : "=r"(b[0]), "=r"(b[1]) : "r"(addr));
}
__device__ __forceinline__ void ldm_x2t(uint32_t* b, uint32_t addr) {
    asm volatile("ldmatrix.sync.aligned.m8n8.x2.trans.shared.b16 {%0,%1}, [%2];"
        : "=r"(b[0]), "=r"(b[1]) : "r"(addr));
}
__device__ __forceinline__ void mma16816(float* c, const uint32_t* a, const uint32_t* b) {
    asm volatile("mma.sync.aligned.m16n8k16.row.col.f32.bf16.bf16.f32 "
        "{%0,%1,%2,%3},{%4,%5,%6,%7},{%8,%9},{%0,%1,%2,%3};"
        : "+f"(c[0]), "+f"(c[1]), "+f"(c[2]), "+f"(c[3])
        : "r"(a[0]), "r"(a[1]), "r"(a[2]), "r"(a[3]), "r"(b[0]), "r"(b[1]));
}
__device__ __forceinline__ void cpa16(uint32_t dst, const void* src) {
    asm volatile("cp.async.cg.shared.global [%0], [%1], 16;" :: "r"(dst), "l"(src));
}
#define CPA_COMMIT() asm volatile("cp.async.commit_group;" ::: "memory")
template<int N>
__device__ __forceinline__ void cpa_wait() {
    asm volatile("cp.async.wait_group %0;" :: "n"(N) : "memory");
}

// NN gemm: A row-major (rows m, k-cols), B row-major rows n, k-cols (used as col-major op)
template<int NK, int ARB, int BRB>
__device__ __forceinline__ void gemm_nn(uint32_t aB, int acb, uint32_t bB, int bcb,
                                        float acc[2][8][4], int lane, int m0, int n0) {
#pragma unroll
    for (int ks = 0; ks < NK; ks++) {
        uint32_t a[2][4];
#pragma unroll
        for (int mt = 0; mt < 2; mt++)
            ldm_x4(a[mt], aB + toff<ARB>(m0 + mt * 16 + (lane & 15),
                                         acb + ks * 32 + ((lane >> 4) << 4)));
#pragma unroll
        for (int nt = 0; nt < 8; nt++) {
            uint32_t b[2];
            ldm_x2(b, bB + toff<BRB>(n0 + nt * 8 + (lane & 7),
                                     bcb + ks * 32 + (((lane >> 3) & 1) << 4)));
            mma16816(acc[0][nt], a[0], b);
            mma16816(acc[1][nt], a[1], b);
        }
    }
}
// NT gemm: B tile stored [k rows][n cols] (trans ldmatrix), k from row 0
template<int NK, int ARB, int BRB>
__device__ __forceinline__ void gemm_nt(uint32_t aB, int acb, uint32_t bB,
                                        float acc[2][8][4], int lane, int m0, int n0) {
#pragma unroll
    for (int ks = 0; ks < NK; ks++) {
        uint32_t a[2][4];
#pragma unroll
        for (int mt = 0; mt < 2; mt++)
            ldm_x4(a[mt], aB + toff<ARB>(m0 + mt * 16 + (lane & 15),
                                         acb + ks * 32 + ((lane >> 4) << 4)));
#pragma unroll
        for (int nt = 0; nt < 8; nt++) {
            uint32_t b[2];
            ldm_x2t(b, bB + toff<BRB>(ks * 16 + (lane & 15), (n0 + nt * 8) * 2));
            mma16816(acc[0][nt], a[0], b);
            mma16816(acc[1][nt], a[1], b);
        }
    }
}
__device__ __forceinline__ void split2(float a, float b, uint32_t& hi, uint32_t& lo) {
    __nv_bfloat16 ha = __float2bfloat16(a), hb = __float2bfloat16(b);
    __nv_bfloat16 la = __float2bfloat16(a - __bfloat162float(ha));
    __nv_bfloat16 lb = __float2bfloat16(b - __bfloat162float(hb));
    hi = ((uint32_t)__bfloat16_as_ushort(hb) << 16) | __bfloat16_as_ushort(ha);
    lo = ((uint32_t)__bfloat16_as_ushort(lb) << 16) | __bfloat16_as_ushort(la);
}
// MUFU-free exp
__device__ __forceinline__ float fast_exp(float x) {
    float y = x * 1.4426950408889634f;
    float z = y + 12582912.0f;
    int   n = __float_as_int(z) - 0x4B400000;
    float f = y - (z - 12582912.0f);
    float p = fmaf(f, 1.5403530e-4f, 1.3333558e-3f);
    p = fmaf(f, p, 9.6181291e-3f);
    p = fmaf(f, p, 5.5504109e-2f);
    p = fmaf(f, p, 2.4022651e-1f);
    p = fmaf(f, p, 6.9314718e-1f);
    p = fmaf(f, p, 1.0f);
    return __int_as_float(__float_as_int(p) + (n << 23));
}
// stage loaders (cp.async): 128x64 tile rb128 (16KB)
__device__ __forceinline__ void stage64(uint32_t dst, const __nv_bfloat16* g, int ld, int t) {
#pragma unroll
    for (int it = 0; it < 4; it++) {
        int idx = t + it * 256, r = idx >> 3, c8 = idx & 7;
        cpa16(dst + toff<128>(r, c8 * 16), g + (size_t)r * ld + c8 * 8);
    }
}
// 128x128 tile rb256 (32KB)
__device__ __forceinline__ void stage128(uint32_t dst, const __nv_bfloat16* g, int ld, int t) {
#pragma unroll
    for (int it = 0; it < 8; it++) {
        int idx = t + it * 256, r = idx >> 4, c8 = idx & 15;
        cpa16(dst + toff<256>(r, c8 * 16), g + (size_t)r * ld + c8 * 8);
    }
}
// 64x128 tile rb256 (16KB)
__device__ __forceinline__ void stage64x128(uint32_t dst, const __nv_bfloat16* g, int ld, int t) {
#pragma unroll
    for (int it = 0; it < 4; it++) {
        int idx = t + it * 256, r = idx >> 4, c8 = idx & 15;
        cpa16(dst + toff<256>(r, c8 * 16), g + (size_t)r * ld + c8 * 8);
    }
}
// fp32 128x64 chunk -> hi/lo width-64 tiles
__device__ __forceinline__ void cvt64(const float* __restrict__ g, int ld,
                                      char* sh, char* sl, int t) {
#pragma unroll
    for (int it = 0; it < 4; it++) {
        int idx = t + it * 256, r = idx >> 3, c8 = idx & 7;
        const float* p = g + (size_t)r * ld + c8 * 8;
        float x[8];
        *(float4*)x = *(const float4*)p;
        *(float4*)(x + 4) = *(const float4*)(p + 4);
        uint32_t h[4], l[4];
#pragma unroll
        for (int j = 0; j < 4; j++) split2(x[j * 2], x[j * 2 + 1], h[j], l[j]);
        uint32_t o = toff<128>(r, c8 * 16);
        *(uint4*)(sh + o) = *(uint4*)h;
        *(uint4*)(sl + o) = *(uint4*)l;
    }
}

// ---------------- prep: Wo fp32 -> hi/lo bf16 rows ----------------
__global__ void __launch_bounds__(256) prep_wo_kernel(const float* __restrict__ Wo) {
    int idx = blockIdx.x * 256 + threadIdx.x;
    int r = idx >> 7, c8 = idx & 127;
    const float* p = Wo + (size_t)r * E + c8 * 8;
    float x[8];
    *(float4*)x = *(const float4*)p;
    *(float4*)(x + 4) = *(const float4*)(p + 4);
    uint32_t h[4], l[4];
#pragma unroll
    for (int j = 0; j < 4; j++) split2(x[j * 2], x[j * 2 + 1], h[j], l[j]);
    *(uint4*)(g_woh + (size_t)r * E + c8 * 8) = *(uint4*)h;
    *(uint4*)(g_wol + (size_t)r * E + c8 * 8) = *(uint4*)l;
}

// ---------------- proj (merged q/k/v): out[s,o] = x[s,:] @ W[o,:]^T ----------------
__global__ void __launch_bounds__(256, 2)
proj_kernel(const float* __restrict__ xq, const float* __restrict__ xk, const float* __restrict__ xv,
            const float* __restrict__ Wq, const float* __restrict__ Wk, const float* __restrict__ Wv) {
    extern __shared__ char sm[];
    uint32_t sb = smem_u32(sm);
    const int t = threadIdx.x, lane = t & 31, wid = t >> 5;
    const int w = blockIdx.x, h = blockIdx.y, z = blockIdx.z;
    const int tz = z / Bb, b = z % Bb;
    const float* x  = (tz == 0) ? xq : (tz == 1) ? xk : xv;
    const float* Wt = (tz == 0) ? Wq : (tz == 1) ? Wk : Wv;
    __nv_bfloat16* oh = (tz == 0) ? g_qh : (tz == 1) ? g_kh : g_vh;
    __nv_bfloat16* ol = (tz == 0) ? g_ql : (tz == 1) ? g_kl : g_vl;
    const float scale = (tz == 0) ? SCALE : 1.0f;

    const int m0 = (wid & 3) * 32, n0 = (wid >> 2) * 64;
    float acc[2][8][4] = {};

    const float* xb = x + ((size_t)(b * S + w * 128)) * E + h * D;
    for (int dc = 0; dc < 2; dc++) {
        __syncthreads();
        cvt64(xb + dc * 64, E, sm, sm + 16384, t);
        cvt64(Wt + dc * 64, D, sm + 32768, sm + 49152, t);
        __syncthreads();
        gemm_nn<4, 128, 128>(sb,         0, sb + 32768, 0, acc, lane, m0, n0);
        gemm_nn<4, 128, 128>(sb,         0, sb + 49152, 0, acc, lane, m0, n0);
        gemm_nn<4, 128, 128>(sb + 16384, 0, sb + 32768, 0, acc, lane, m0, n0);
    }

    size_t base = ((size_t)(b * H + h) * S + w * 128);
#pragma unroll
    for (int mt = 0; mt < 2; mt++)
#pragma unroll
        for (int hf = 0; hf < 2; hf++) {
            int r = m0 + mt * 16 + (lane >> 2) + hf * 8;
            size_t row = (base + r) * D;
#pragma unroll
            for (int nt = 0; nt < 8; nt++) {
                int c = n0 + nt * 8 + (lane & 3) * 2;
                uint32_t hi, lo;
                split2(acc[mt][nt][hf * 2] * scale, acc[mt][nt][hf * 2 + 1] * scale, hi, lo);
                *(uint32_t*)(oh + row + c) = hi;
                *(uint32_t*)(ol + row + c) = lo;
            }
        }
}

// ---------------- attention: pipelined stages ----------------
// smem: Qh 0 | Ql 32K | Ph 64K | Pl 96K | buf0 128K | buf1 160K | Lacc 192K
__global__ void __launch_bounds__(256)
attn_kernel() {
    extern __shared__ char sm[];
    uint32_t sb = smem_u32(sm);
    float* Lacc = (float*)(sm + 196608);
    const int t = threadIdx.x, lane = t & 31, wid = t >> 5;
    const int w = blockIdx.x, h = blockIdx.y, b = blockIdx.z;
    const size_t base = (size_t)((b * H + h) * S);
    const int m0 = (wid & 3) * 32, n0 = (wid >> 2) * 64;

    const int j0 = (w > 0) ? w - 1 : 0;
    const int j1 = (w < NW - 1) ? w + 1 : NW - 1;
    const int nstep = (j1 - j0 + 1) * 4;
    const uint32_t bufs[2] = { sb + 131072, sb + 163840 };

    auto issue_stage = [&](int ts) {
        if (ts >= nstep) return;
        int j = j0 + (ts >> 2), kind = ts & 3;
        uint32_t bf = bufs[ts & 1];
        size_t roff = (base + (size_t)j * 128) * D;
        if (kind < 2) {
            stage64(bf,         g_kh + roff + kind * 64, D, t);
            stage64(bf + 16384, g_kl + roff + kind * 64, D, t);
        } else {
            size_t so = roff + (size_t)(kind - 2) * 64 * D;
            stage64x128(bf,         g_vh + so, D, t);
            stage64x128(bf + 16384, g_vl + so, D, t);
        }
    };

    if (t < 128) Lacc[t] = 0.0f;
    stage128(sb,         g_qh + (base + (size_t)w * 128) * D, D, t);
    stage128(sb + 32768, g_ql + (base + (size_t)w * 128) * D, D, t);
    issue_stage(0);
    CPA_COMMIT();

    float oacc[2][8][4] = {};
    float sacc[2][8][4];

    for (int ts = 0; ts < nstep; ts++) {
        issue_stage(ts + 1);
        CPA_COMMIT();
        cpa_wait<1>();
        __syncthreads();
        const uint32_t bf = bufs[ts & 1];
        const int kind = ts & 3;
        if (kind < 2) {
            if (kind == 0) {
#pragma unroll
                for (int i = 0; i < 2; i++)
#pragma unroll
                    for (int j = 0; j < 8; j++)
#pragma unroll
                        for (int q = 0; q < 4; q++) sacc[i][j][q] = 0.0f;
            }
            gemm_nn<4, 256, 128>(sb,         kind * 128, bf,         0, sacc, lane, m0, n0);
            gemm_nn<4, 256, 128>(sb,         kind * 128, bf + 16384, 0, sacc, lane, m0, n0);
            gemm_nn<4, 256, 128>(sb + 32768, kind * 128, bf,         0, sacc, lane, m0, n0);
            if (kind == 1) {  // exp -> P hi/lo tiles, accumulate row sums
#pragma unroll
                for (int mt = 0; mt < 2; mt++)
#pragma unroll
                    for (int hf = 0; hf < 2; hf++) {
                        int r = m0 + mt * 16 + (lane >> 2) + hf * 8;
                        float rsum = 0.0f;
#pragma unroll
                        for (int nt = 0; nt < 8; nt++) {
                            float e0 = fast_exp(sacc[mt][nt][hf * 2]);
                            float e1 = fast_exp(sacc[mt][nt][hf * 2 + 1]);
                            rsum += e0 + e1;
                            uint32_t hi, lo;
                            split2(e0, e1, hi, lo);
                            int c = n0 + nt * 8 + (lane & 3) * 2;
                            uint32_t o = toff<256>(r, c * 2);
                            *(uint32_t*)(sm + 65536 + o) = hi;
                            *(uint32_t*)(sm + 98304 + o) = lo;
                        }
                        rsum += __shfl_xor_sync(0xffffffffu, rsum, 1);
                        rsum += __shfl_xor_sync(0xffffffffu, rsum, 2);
                        if ((lane & 3) == 0) atomicAdd(&Lacc[r], rsum);
                    }
            }
        } else {
            const int sc = kind - 2;
            gemm_nt<4, 256, 256>(sb + 65536, sc * 128, bf,         oacc, lane, m0, n0);
            gemm_nt<4, 256, 256>(sb + 65536, sc * 128, bf + 16384, oacc, lane, m0, n0);
            gemm_nt<4, 256, 256>(sb + 98304, sc * 128, bf,         oacc, lane, m0, n0);
        }
        __syncthreads();
    }

#pragma unroll
    for (int mt = 0; mt < 2; mt++)
#pragma unroll
        for (int hf = 0; hf < 2; hf++) {
            int r = m0 + mt * 16 + (lane >> 2) + hf * 8;
            float inv = 1.0f / Lacc[r];
            size_t row = ((size_t)b * S + w * 128 + r) * E + h * D;
#pragma unroll
            for (int nt = 0; nt < 8; nt++) {
                int c = n0 + nt * 8 + (lane & 3) * 2;
                uint32_t hi, lo;
                split2(oacc[mt][nt][hf * 2] * inv, oacc[mt][nt][hf * 2 + 1] * inv, hi, lo);
                *(uint32_t*)(g_ah + row + c) = hi;
                *(uint32_t*)(g_al + row + c) = lo;
            }
        }
}

// ---------------- fc: y = att @ Wo^T + bo, K=32 ping-pong stages ----------------
// smem: Ah 0 | Al 16K | Wh 32K | Wl 48K (each width-64 tile = two K=32 column halves)
__global__ void __launch_bounds__(256, 2)
fc_kernel(const float* __restrict__ bo, float* __restrict__ y) {
    extern __shared__ char sm[];
    uint32_t sb = smem_u32(sm);
    const int t = threadIdx.x, lane = t & 31, wid = t >> 5;
    const int nb = blockIdx.x, mb = blockIdx.y;
    const int m0 = (wid & 3) * 32, n0 = (wid >> 2) * 64;

    auto issue_stage = [&](int s) {
        if (s >= 32) return;
        int half = (s & 1) * 64;  // column-half byte offset
#pragma unroll
        for (int it = 0; it < 2; it++) {
            int idx = t + it * 256, r = idx >> 2, c2 = idx & 3;
            uint32_t o = toff<128>(r, half + c2 * 16);
            size_t asrc = (size_t)(mb * 128 + r) * E + s * 32 + c2 * 8;
            size_t wsrc = (size_t)(nb * 128 + r) * E + s * 32 + c2 * 8;
            cpa16(sb         + o, g_ah  + asrc);
            cpa16(sb + 16384 + o, g_al  + asrc);
            cpa16(sb + 32768 + o, g_woh + wsrc);
            cpa16(sb + 49152 + o, g_wol + wsrc);
        }
    };

    issue_stage(0);
    CPA_COMMIT();

    float acc[2][8][4] = {};
    for (int s = 0; s < 32; s++) {
        issue_stage(s + 1);
        CPA_COMMIT();
        cpa_wait<1>();
        __syncthreads();
        const int cb = (s & 1) * 64;
        gemm_nn<2, 128, 128>(sb,         cb, sb + 32768, cb, acc, lane, m0, n0);
        gemm_nn<2, 128, 128>(sb,         cb, sb + 49152, cb, acc, lane, m0, n0);
        gemm_nn<2, 128, 128>(sb + 16384, cb, sb + 32768, cb, acc, lane, m0, n0);
        __syncthreads();
    }

#pragma unroll
    for (int mt = 0; mt < 2; mt++)
#pragma unroll
        for (int hf = 0; hf < 2; hf++) {
            int r = m0 + mt * 16 + (lane >> 2) + hf * 8;
            size_t row = ((size_t)(mb * 128 + r)) * E + nb * 128;
#pragma unroll
            for (int nt = 0; nt < 8; nt++) {
                int c = n0 + nt * 8 + (lane & 3) * 2;
                float2 o;
                o.x = acc[mt][nt][hf * 2]     + bo[nb * 128 + c];
                o.y = acc[mt][nt][hf * 2 + 1] + bo[nb * 128 + c + 1];
                *(float2*)(y + row + c) = o;
            }
        }
}

// ---------------- launcher ----------------
extern "C" void kernel_launch(void* const* d_in, const int* in_sizes, int n_in,
                              void* d_out, int out_size) {
    const float* values = (const float*)d_in[0];
    const float* keys   = (const float*)d_in[1];
    const float* query  = (const float*)d_in[2];
    const float* Wv     = (const float*)d_in[3];
    const float* Wk     = (const float*)d_in[4];
    const float* Wq     = (const float*)d_in[5];
    const float* Wo     = (const float*)d_in[6];
    const float* bo     = (const float*)d_in[7];
    float* out = (float*)d_out;

    const int proj_smem = 65536;
    const int attn_smem = 196608 + 512;
    const int fc_smem   = 65536;
    cudaFuncSetAttribute(proj_kernel, cudaFuncAttributeMaxDynamicSharedMemorySize, proj_smem);
    cudaFuncSetAttribute(attn_kernel, cudaFuncAttributeMaxDynamicSharedMemorySize, attn_smem);
    cudaFuncSetAttribute(fc_kernel,   cudaFuncAttributeMaxDynamicSharedMemorySize, fc_smem);

    prep_wo_kernel<<<512, 256>>>(Wo);

    proj_kernel<<<dim3(NW, H, 3 * Bb), 256, proj_smem>>>(query, keys, values, Wq, Wk, Wv);

    attn_kernel<<<dim3(NW, H, Bb), 256, attn_smem>>>();

    fc_kernel<<<dim3(E / 128, (Bb * S) / 128), 256, fc_smem>>>(bo, out);
}

// round 9
// speedup vs baseline: 3.2574x; 1.1389x over previous
#include <cuda_runtime.h>
#include <cuda_bf16.h>
#include <cstdint>

namespace {
constexpr int Bb = 8, S = 4096, E = 1024, H = 8, D = 128, NW = 32;
constexpr float SCALE = 0.08838834764831845f;  // D^-0.5
}

// intermediates (device globals; no runtime alloc). q,k: hi only (single-pass QK).
__device__ __align__(128) __nv_bfloat16 g_qh[(size_t)Bb*H*S*D];
__device__ __align__(128) __nv_bfloat16 g_kh[(size_t)Bb*H*S*D];
__device__ __align__(128) __nv_bfloat16 g_vh[(size_t)Bb*H*S*D], g_vl[(size_t)Bb*H*S*D];
__device__ __align__(128) __nv_bfloat16 g_ah[(size_t)Bb*S*E],   g_al[(size_t)Bb*S*E];
__device__ __align__(128) __nv_bfloat16 g_woh[(size_t)E*E],     g_wol[(size_t)E*E];

// ---------------- low-level helpers ----------------
__device__ __forceinline__ uint32_t smem_u32(const void* p) {
    uint32_t a;
    asm("{ .reg .u64 t; cvta.to.shared.u64 t, %1; cvt.u32.u64 %0, t; }" : "=r"(a) : "l"(p));
    return a;
}
template<int RB>
__device__ __forceinline__ uint32_t toff(int r, int cb) {
    return (uint32_t)(r * RB + ((((cb >> 4) ^ (r & 7)) & (RB / 16 - 1)) << 4) + (cb & 15));
}
__device__ __forceinline__ void ldm_x4(uint32_t* a, uint32_t addr) {
    asm volatile("ldmatrix.sync.aligned.m8n8.x4.shared.b16 {%0,%1,%2,%3}, [%4];"
        : "=r"(a[0]), "=r"(a[1]), "=r"(a[2]), "=r"(a[3]) : "r"(addr));
}
__device__ __forceinline__ void ldm_x2(uint32_t* b, uint32_t addr) {
    asm volatile("ldmatrix.sync.aligned.m8n8.x2.shared.b16 {%0,%1}, [%2];"
        : "=r"(b[0]), "=r"(b[1]) : "r"(addr));
}
__device__ __forceinline__ void ldm_x2t(uint32_t* b, uint32_t addr) {
    asm volatile("ldmatrix.sync.aligned.m8n8.x2.trans.shared.b16 {%0,%1}, [%2];"
        : "=r"(b[0]), "=r"(b[1]) : "r"(addr));
}
__device__ __forceinline__ void mma16816(float* c, const uint32_t* a, const uint32_t* b) {
    asm volatile("mma.sync.aligned.m16n8k16.row.col.f32.bf16.bf16.f32 "
        "{%0,%1,%2,%3},{%4,%5,%6,%7},{%8,%9},{%0,%1,%2,%3};"
        : "+f"(c[0]), "+f"(c[1]), "+f"(c[2]), "+f"(c[3])
        : "r"(a[0]), "r"(a[1]), "r"(a[2]), "r"(a[3]), "r"(b[0]), "r"(b[1]));
}
__device__ __forceinline__ void cpa16(uint32_t dst, const void* src) {
    asm volatile("cp.async.cg.shared.global [%0], [%1], 16;" :: "r"(dst), "l"(src));
}
#define CPA_COMMIT() asm volatile("cp.async.commit_group;" ::: "memory")
template<int N>
__device__ __forceinline__ void cpa_wait() {
    asm volatile("cp.async.wait_group %0;" :: "n"(N) : "memory");
}

template<int NK, int ARB, int BRB>
__device__ __forceinline__ void gemm_nn(uint32_t aB, int acb, uint32_t bB, int bcb,
                                        float acc[2][8][4], int lane, int m0, int n0) {
#pragma unroll
    for (int ks = 0; ks < NK; ks++) {
        uint32_t a[2][4];
#pragma unroll
        for (int mt = 0; mt < 2; mt++)
            ldm_x4(a[mt], aB + toff<ARB>(m0 + mt * 16 + (lane & 15),
                                         acb + ks * 32 + ((lane >> 4) << 4)));
#pragma unroll
        for (int nt = 0; nt < 8; nt++) {
            uint32_t b[2];
            ldm_x2(b, bB + toff<BRB>(n0 + nt * 8 + (lane & 7),
                                     bcb + ks * 32 + (((lane >> 3) & 1) << 4)));
            mma16816(acc[0][nt], a[0], b);
            mma16816(acc[1][nt], a[1], b);
        }
    }
}
template<int NK, int ARB, int BRB>
__device__ __forceinline__ void gemm_nt(uint32_t aB, int acb, uint32_t bB,
                                        float acc[2][8][4], int lane, int m0, int n0) {
#pragma unroll
    for (int ks = 0; ks < NK; ks++) {
        uint32_t a[2][4];
#pragma unroll
        for (int mt = 0; mt < 2; mt++)
            ldm_x4(a[mt], aB + toff<ARB>(m0 + mt * 16 + (lane & 15),
                                         acb + ks * 32 + ((lane >> 4) << 4)));
#pragma unroll
        for (int nt = 0; nt < 8; nt++) {
            uint32_t b[2];
            ldm_x2t(b, bB + toff<BRB>(ks * 16 + (lane & 15), (n0 + nt * 8) * 2));
            mma16816(acc[0][nt], a[0], b);
            mma16816(acc[1][nt], a[1], b);
        }
    }
}
__device__ __forceinline__ void split2(float a, float b, uint32_t& hi, uint32_t& lo) {
    __nv_bfloat16 ha = __float2bfloat16(a), hb = __float2bfloat16(b);
    __nv_bfloat16 la = __float2bfloat16(a - __bfloat162float(ha));
    __nv_bfloat16 lb = __float2bfloat16(b - __bfloat162float(hb));
    hi = ((uint32_t)__bfloat16_as_ushort(hb) << 16) | __bfloat16_as_ushort(ha);
    lo = ((uint32_t)__bfloat16_as_ushort(lb) << 16) | __bfloat16_as_ushort(la);
}
__device__ __forceinline__ uint32_t pack2h(float a, float b) {
    return ((uint32_t)__bfloat16_as_ushort(__float2bfloat16(b)) << 16) |
           __bfloat16_as_ushort(__float2bfloat16(a));
}
__device__ __forceinline__ float fast_exp(float x) {
    float y = x * 1.4426950408889634f;
    float z = y + 12582912.0f;
    int   n = __float_as_int(z) - 0x4B400000;
    float f = y - (z - 12582912.0f);
    float p = fmaf(f, 1.5403530e-4f, 1.3333558e-3f);
    p = fmaf(f, p, 9.6181291e-3f);
    p = fmaf(f, p, 5.5504109e-2f);
    p = fmaf(f, p, 2.4022651e-1f);
    p = fmaf(f, p, 6.9314718e-1f);
    p = fmaf(f, p, 1.0f);
    return __int_as_float(__float_as_int(p) + (n << 23));
}
// stage loaders (cp.async)
__device__ __forceinline__ void stage128(uint32_t dst, const __nv_bfloat16* g, int ld, int t) {
#pragma unroll
    for (int it = 0; it < 8; it++) {
        int idx = t + it * 256, r = idx >> 4, c8 = idx & 15;
        cpa16(dst + toff<256>(r, c8 * 16), g + (size_t)r * ld + c8 * 8);
    }
}
__device__ __forceinline__ void stage64x128(uint32_t dst, const __nv_bfloat16* g, int ld, int t) {
#pragma unroll
    for (int it = 0; it < 4; it++) {
        int idx = t + it * 256, r = idx >> 4, c8 = idx & 15;
        cpa16(dst + toff<256>(r, c8 * 16), g + (size_t)r * ld + c8 * 8);
    }
}
__device__ __forceinline__ void cvt64(const float* __restrict__ g, int ld,
                                      char* sh, char* sl, int t) {
#pragma unroll
    for (int it = 0; it < 4; it++) {
        int idx = t + it * 256, r = idx >> 3, c8 = idx & 7;
        const float* p = g + (size_t)r * ld + c8 * 8;
        float x[8];
        *(float4*)x = *(const float4*)p;
        *(float4*)(x + 4) = *(const float4*)(p + 4);
        uint32_t h[4], l[4];
#pragma unroll
        for (int j = 0; j < 4; j++) split2(x[j * 2], x[j * 2 + 1], h[j], l[j]);
        uint32_t o = toff<128>(r, c8 * 16);
        *(uint4*)(sh + o) = *(uint4*)h;
        *(uint4*)(sl + o) = *(uint4*)l;
    }
}

// ---------------- prep: Wo fp32 -> hi/lo bf16 rows ----------------
__global__ void __launch_bounds__(256) prep_wo_kernel(const float* __restrict__ Wo) {
    int idx = blockIdx.x * 256 + threadIdx.x;
    int r = idx >> 7, c8 = idx & 127;
    const float* p = Wo + (size_t)r * E + c8 * 8;
    float x[8];
    *(float4*)x = *(const float4*)p;
    *(float4*)(x + 4) = *(const float4*)(p + 4);
    uint32_t h[4], l[4];
#pragma unroll
    for (int j = 0; j < 4; j++) split2(x[j * 2], x[j * 2 + 1], h[j], l[j]);
    *(uint4*)(g_woh + (size_t)r * E + c8 * 8) = *(uint4*)h;
    *(uint4*)(g_wol + (size_t)r * E + c8 * 8) = *(uint4*)l;
}

// ---------------- proj (merged q/k/v), 3-term; q/k store hi only ----------------
__global__ void __launch_bounds__(256, 2)
proj_kernel(const float* __restrict__ xq, const float* __restrict__ xk, const float* __restrict__ xv,
            const float* __restrict__ Wq, const float* __restrict__ Wk, const float* __restrict__ Wv) {
    extern __shared__ char sm[];
    uint32_t sb = smem_u32(sm);
    const int t = threadIdx.x, lane = t & 31, wid = t >> 5;
    const int w = blockIdx.x, h = blockIdx.y, z = blockIdx.z;
    const int tz = z / Bb, b = z % Bb;
    const float* x  = (tz == 0) ? xq : (tz == 1) ? xk : xv;
    const float* Wt = (tz == 0) ? Wq : (tz == 1) ? Wk : Wv;
    __nv_bfloat16* oh = (tz == 0) ? g_qh : (tz == 1) ? g_kh : g_vh;
    const float scale = (tz == 0) ? SCALE : 1.0f;

    const int m0 = (wid & 3) * 32, n0 = (wid >> 2) * 64;
    float acc[2][8][4] = {};

    const float* xb = x + ((size_t)(b * S + w * 128)) * E + h * D;
    for (int dc = 0; dc < 2; dc++) {
        __syncthreads();
        cvt64(xb + dc * 64, E, sm, sm + 16384, t);
        cvt64(Wt + dc * 64, D, sm + 32768, sm + 49152, t);
        __syncthreads();
        gemm_nn<4, 128, 128>(sb,         0, sb + 32768, 0, acc, lane, m0, n0);
        gemm_nn<4, 128, 128>(sb,         0, sb + 49152, 0, acc, lane, m0, n0);
        gemm_nn<4, 128, 128>(sb + 16384, 0, sb + 32768, 0, acc, lane, m0, n0);
    }

    size_t base = ((size_t)(b * H + h) * S + w * 128);
#pragma unroll
    for (int mt = 0; mt < 2; mt++)
#pragma unroll
        for (int hf = 0; hf < 2; hf++) {
            int r = m0 + mt * 16 + (lane >> 2) + hf * 8;
            size_t row = (base + r) * D;
#pragma unroll
            for (int nt = 0; nt < 8; nt++) {
                int c = n0 + nt * 8 + (lane & 3) * 2;
                float v0 = acc[mt][nt][hf * 2] * scale, v1 = acc[mt][nt][hf * 2 + 1] * scale;
                if (tz < 2) {
                    *(uint32_t*)(oh + row + c) = pack2h(v0, v1);
                } else {
                    uint32_t hi, lo;
                    split2(v0, v1, hi, lo);
                    *(uint32_t*)(g_vh + row + c) = hi;
                    *(uint32_t*)(g_vl + row + c) = lo;
                }
            }
        }
}

// ---------------- attention: single-pass QK, 3-term PV, 3 stages/window ----------------
// smem: Qh 0 | Ph 32K | Pl 64K | buf0 96K | buf1 128K | Lacc 160K
__global__ void __launch_bounds__(256)
attn_kernel() {
    extern __shared__ char sm[];
    uint32_t sb = smem_u32(sm);
    float* Lacc = (float*)(sm + 163840);
    const int t = threadIdx.x, lane = t & 31, wid = t >> 5;
    const int w = blockIdx.x, h = blockIdx.y, b = blockIdx.z;
    const size_t base = (size_t)((b * H + h) * S);
    const int m0 = (wid & 3) * 32, n0 = (wid >> 2) * 64;

    const int j0 = (w > 0) ? w - 1 : 0;
    const int j1 = (w < NW - 1) ? w + 1 : NW - 1;
    const int nstep = (j1 - j0 + 1) * 3;
    const uint32_t bufs[2] = { sb + 98304, sb + 131072 };

    auto issue_stage = [&](int ts) {
        if (ts >= nstep) return;
        int j = j0 + ts / 3, kind = ts % 3;
        uint32_t bf = bufs[ts & 1];
        size_t roff = (base + (size_t)j * 128) * D;
        if (kind == 0) {
            stage128(bf, g_kh + roff, D, t);
        } else {
            size_t so = roff + (size_t)(kind - 1) * 64 * D;
            stage64x128(bf,         g_vh + so, D, t);
            stage64x128(bf + 16384, g_vl + so, D, t);
        }
    };

    if (t < 128) Lacc[t] = 0.0f;
    stage128(sb, g_qh + (base + (size_t)w * 128) * D, D, t);
    issue_stage(0);
    CPA_COMMIT();

    float oacc[2][8][4] = {};

    for (int ts = 0; ts < nstep; ts++) {
        cpa_wait<0>();
        __syncthreads();          // stage ts visible; all warps done with buf being overwritten
        issue_stage(ts + 1);
        CPA_COMMIT();
        const uint32_t bf = bufs[ts & 1];
        const int kind = ts % 3;
        if (kind == 0) {
            float sacc[2][8][4] = {};
            gemm_nn<8, 256, 256>(sb, 0, bf, 0, sacc, lane, m0, n0);   // S = q·k^T (hi only)
#pragma unroll
            for (int mt = 0; mt < 2; mt++)
#pragma unroll
                for (int hf = 0; hf < 2; hf++) {
                    int r = m0 + mt * 16 + (lane >> 2) + hf * 8;
                    float rsum = 0.0f;
#pragma unroll
                    for (int nt = 0; nt < 8; nt++) {
                        float e0 = fast_exp(sacc[mt][nt][hf * 2]);
                        float e1 = fast_exp(sacc[mt][nt][hf * 2 + 1]);
                        rsum += e0 + e1;
                        uint32_t hi, lo;
                        split2(e0, e1, hi, lo);
                        int c = n0 + nt * 8 + (lane & 3) * 2;
                        uint32_t o = toff<256>(r, c * 2);
                        *(uint32_t*)(sm + 32768 + o) = hi;
                        *(uint32_t*)(sm + 65536 + o) = lo;
                    }
                    rsum += __shfl_xor_sync(0xffffffffu, rsum, 1);
                    rsum += __shfl_xor_sync(0xffffffffu, rsum, 2);
                    if ((lane & 3) == 0) atomicAdd(&Lacc[r], rsum);
                }
        } else {
            const int sc = kind - 1;
            gemm_nt<4, 256, 256>(sb + 32768, sc * 128, bf,         oacc, lane, m0, n0);
            gemm_nt<4, 256, 256>(sb + 32768, sc * 128, bf + 16384, oacc, lane, m0, n0);
            gemm_nt<4, 256, 256>(sb + 65536, sc * 128, bf,         oacc, lane, m0, n0);
        }
    }
    __syncthreads();

#pragma unroll
    for (int mt = 0; mt < 2; mt++)
#pragma unroll
        for (int hf = 0; hf < 2; hf++) {
            int r = m0 + mt * 16 + (lane >> 2) + hf * 8;
            float inv = 1.0f / Lacc[r];
            size_t row = ((size_t)b * S + w * 128 + r) * E + h * D;
#pragma unroll
            for (int nt = 0; nt < 8; nt++) {
                int c = n0 + nt * 8 + (lane & 3) * 2;
                uint32_t hi, lo;
                split2(oacc[mt][nt][hf * 2] * inv, oacc[mt][nt][hf * 2 + 1] * inv, hi, lo);
                *(uint32_t*)(g_ah + row + c) = hi;
                *(uint32_t*)(g_al + row + c) = lo;
            }
        }
}

// ---------------- fc: y = att @ Wo^T + bo, K=32 ping-pong, one sync/stage ----------------
__global__ void __launch_bounds__(256, 2)
fc_kernel(const float* __restrict__ bo, float* __restrict__ y) {
    extern __shared__ char sm[];
    uint32_t sb = smem_u32(sm);
    const int t = threadIdx.x, lane = t & 31, wid = t >> 5;
    const int nb = blockIdx.x, mb = blockIdx.y;
    const int m0 = (wid & 3) * 32, n0 = (wid >> 2) * 64;

    auto issue_stage = [&](int s) {
        if (s >= 32) return;
        int half = (s & 1) * 64;
#pragma unroll
        for (int it = 0; it < 2; it++) {
            int idx = t + it * 256, r = idx >> 2, c2 = idx & 3;
            uint32_t o = toff<128>(r, half + c2 * 16);
            size_t asrc = (size_t)(mb * 128 + r) * E + s * 32 + c2 * 8;
            size_t wsrc = (size_t)(nb * 128 + r) * E + s * 32 + c2 * 8;
            cpa16(sb         + o, g_ah  + asrc);
            cpa16(sb + 16384 + o, g_al  + asrc);
            cpa16(sb + 32768 + o, g_woh + wsrc);
            cpa16(sb + 49152 + o, g_wol + wsrc);
        }
    };

    issue_stage(0);
    CPA_COMMIT();

    float acc[2][8][4] = {};
    for (int s = 0; s < 32; s++) {
        cpa_wait<0>();
        __syncthreads();
        issue_stage(s + 1);
        CPA_COMMIT();
        const int cb = (s & 1) * 64;
        gemm_nn<2, 128, 128>(sb,         cb, sb + 32768, cb, acc, lane, m0, n0);
        gemm_nn<2, 128, 128>(sb,         cb, sb + 49152, cb, acc, lane, m0, n0);
        gemm_nn<2, 128, 128>(sb + 16384, cb, sb + 32768, cb, acc, lane, m0, n0);
    }

#pragma unroll
    for (int mt = 0; mt < 2; mt++)
#pragma unroll
        for (int hf = 0; hf < 2; hf++) {
            int r = m0 + mt * 16 + (lane >> 2) + hf * 8;
            size_t row = ((size_t)(mb * 128 + r)) * E + nb * 128;
#pragma unroll
            for (int nt = 0; nt < 8; nt++) {
                int c = n0 + nt * 8 + (lane & 3) * 2;
                float2 o;
                o.x = acc[mt][nt][hf * 2]     + bo[nb * 128 + c];
                o.y = acc[mt][nt][hf * 2 + 1] + bo[nb * 128 + c + 1];
                *(float2*)(y + row + c) = o;
            }
        }
}

// ---------------- launcher ----------------
extern "C" void kernel_launch(void* const* d_in, const int* in_sizes, int n_in,
                              void* d_out, int out_size) {
    const float* values = (const float*)d_in[0];
    const float* keys   = (const float*)d_in[1];
    const float* query  = (const float*)d_in[2];
    const float* Wv     = (const float*)d_in[3];
    const float* Wk     = (const float*)d_in[4];
    const float* Wq     = (const float*)d_in[5];
    const float* Wo     = (const float*)d_in[6];
    const float* bo     = (const float*)d_in[7];
    float* out = (float*)d_out;

    const int proj_smem = 65536;
    const int attn_smem = 163840 + 512;
    const int fc_smem   = 65536;
    cudaFuncSetAttribute(proj_kernel, cudaFuncAttributeMaxDynamicSharedMemorySize, proj_smem);
    cudaFuncSetAttribute(attn_kernel, cudaFuncAttributeMaxDynamicSharedMemorySize, attn_smem);
    cudaFuncSetAttribute(fc_kernel,   cudaFuncAttributeMaxDynamicSharedMemorySize, fc_smem);

    prep_wo_kernel<<<512, 256>>>(Wo);

    proj_kernel<<<dim3(NW, H, 3 * Bb), 256, proj_smem>>>(query, keys, values, Wq, Wk, Wv);

    attn_kernel<<<dim3(NW, H, Bb), 256, attn_smem>>>();

    fc_kernel<<<dim3(E / 128, (Bb * S) / 128), 256, fc_smem>>>(bo, out);
}